// round 9
// baseline (speedup 1.0000x reference)
#include <cuda_runtime.h>
#include <cstdint>

// SurfEval: NURBS surface evaluation. B=8, M=N=64, P=Q=3, GRID=512, DIM=3.
//
// R9 change: output stores moved OFF the LSU. Stage B writes results to a
// contiguous smem staging buffer (conflict-free STS.128, 48B lane stride),
// then one elected thread TMA-bulk-copies each 6144B g-line row to gmem
// (cp.async.bulk shared->global). STG.128 was 44% of the per-block L1 bill
// and pinned warp scoreboards; TMA drains via the async proxy instead.

#define GRID_N 512
#define MCTRL 64
#define NCTRL 64
#define ROWF4 (GRID_N * 3 / 4)   // 384 float4 per (b,g) output row

// Precomputed Stage-B tables (t = 0..127): 5-tap shifted weights, window base.
__device__ float4 g_W4[4][128];   // taps 0..3 for point k of thread t
__device__ float  g_W1[4][128];   // tap 4
__device__ int    g_J[128];       // j0 = vspan[4t] - 3

// ---------------- Kernel 0: weight table (1 block, 128 threads) ----------------
__global__ void weight_kernel(const int4* __restrict__ vspan4,
                              const float4* __restrict__ Nv)
{
    const int t = threadIdx.x;
    const int4 vsv = __ldg(vspan4 + t);
    g_J[t] = vsv.x - 3;
    const int vs[4] = {vsv.x, vsv.y, vsv.z, vsv.w};
#pragma unroll
    for (int k = 0; k < 4; ++k) {
        const float4 nv = __ldg(Nv + 4 * t + k);
        const bool s = (vs[k] != vsv.x);   // span delta 0 or 1 (guaranteed)
        g_W4[k][t] = make_float4(s ? 0.0f : nv.x,
                                 s ? nv.x : nv.y,
                                 s ? nv.y : nv.z,
                                 s ? nv.z : nv.w);
        g_W1[k][t] = s ? nv.w : 0.0f;
    }
}

// ---------------- Kernel 1: fused surface eval (g-pair blocks) ----------------
__global__ __launch_bounds__(128, 9) void surf_eval_kernel(
    const float4* __restrict__ ctrl,   // (B, 64, 64) float4
    const int*    __restrict__ uspan,  // (512)
    const float4* __restrict__ Nu,     // (512) float4
    float4*       __restrict__ out)    // (B*512*512*3)/4 float4
{
    __shared__ float4 Su[2][NCTRL + 1];     // [gg][n], +1 zero guard at n=64
    __shared__ float4 obuf[2][ROWF4];       // staging: 2 x 6144 B output rows

    const int g0 = blockIdx.x << 1;
    const int b  = blockIdx.y;
    const int t  = threadIdx.x;

    // ---- Prefetch Stage-B tables (coalesced; overlaps Stage-A latency) ----
    const int j0 = __ldg(g_J + t);
    float4 w4[4];
    float  w1[4];
#pragma unroll
    for (int k = 0; k < 4; ++k) {
        w4[k] = __ldg(&g_W4[k][t]);
        w1[k] = __ldg(&g_W1[k][t]);
    }

    // ---- Stage A: Su[gg][n] = sum_r Nu[g0+gg,r] * ctrl[b, us-3+r, n, :] ----
    {
        const int us0 = __ldg(uspan + g0);
        const int us1 = __ldg(uspan + g0 + 1);
        const int n    = t & 63;
        const int half = t >> 6;

        if (us0 == us1) {
            if (half == 0) {
                const float4 nu0 = __ldg(Nu + g0);
                const float4 nu1 = __ldg(Nu + g0 + 1);
                const float4* base = ctrl + (b * MCTRL + (us0 - 3)) * NCTRL + n;
                const float4 c0 = __ldg(base);
                const float4 c1 = __ldg(base + NCTRL);
                const float4 c2 = __ldg(base + 2 * NCTRL);
                const float4 c3 = __ldg(base + 3 * NCTRL);
                float4 a;
                a.x = nu0.x * c0.x + nu0.y * c1.x + nu0.z * c2.x + nu0.w * c3.x;
                a.y = nu0.x * c0.y + nu0.y * c1.y + nu0.z * c2.y + nu0.w * c3.y;
                a.z = nu0.x * c0.z + nu0.y * c1.z + nu0.z * c2.z + nu0.w * c3.z;
                a.w = nu0.x * c0.w + nu0.y * c1.w + nu0.z * c2.w + nu0.w * c3.w;
                Su[0][n] = a;
                a.x = nu1.x * c0.x + nu1.y * c1.x + nu1.z * c2.x + nu1.w * c3.x;
                a.y = nu1.x * c0.y + nu1.y * c1.y + nu1.z * c2.y + nu1.w * c3.y;
                a.z = nu1.x * c0.z + nu1.y * c1.z + nu1.z * c2.z + nu1.w * c3.z;
                a.w = nu1.x * c0.w + nu1.y * c1.w + nu1.z * c2.w + nu1.w * c3.w;
                Su[1][n] = a;
            }
        } else {
            const int    us = half ? us1 : us0;
            const float4 nu = __ldg(Nu + g0 + half);
            const float4* base = ctrl + (b * MCTRL + (us - 3)) * NCTRL + n;
            const float4 c0 = __ldg(base);
            const float4 c1 = __ldg(base + NCTRL);
            const float4 c2 = __ldg(base + 2 * NCTRL);
            const float4 c3 = __ldg(base + 3 * NCTRL);
            float4 a;
            a.x = nu.x * c0.x + nu.y * c1.x + nu.z * c2.x + nu.w * c3.x;
            a.y = nu.x * c0.y + nu.y * c1.y + nu.z * c2.y + nu.w * c3.y;
            a.z = nu.x * c0.z + nu.y * c1.z + nu.z * c2.z + nu.w * c3.z;
            a.w = nu.x * c0.w + nu.y * c1.w + nu.z * c2.w + nu.w * c3.w;
            Su[half][n] = a;
        }
        if (t == 124) Su[0][NCTRL] = make_float4(0.f, 0.f, 0.f, 0.f);
        if (t == 125) Su[1][NCTRL] = make_float4(0.f, 0.f, 0.f, 0.f);
    }
    __syncthreads();

    // ---- Stage B: 4 h points x 2 g-lines -> smem staging (no STG) ----
#pragma unroll
    for (int gg = 0; gg < 2; ++gg) {
        const float4* SuG = Su[gg];
        const float4 q0 = SuG[j0];
        const float4 q1 = SuG[j0 + 1];
        const float4 q2 = SuG[j0 + 2];
        const float4 q3 = SuG[j0 + 3];
        const float4 q4 = SuG[j0 + 4];

        float r[12];
#pragma unroll
        for (int k = 0; k < 4; ++k) {
            const float X = w4[k].x * q0.x + w4[k].y * q1.x + w4[k].z * q2.x + w4[k].w * q3.x + w1[k] * q4.x;
            const float Y = w4[k].x * q0.y + w4[k].y * q1.y + w4[k].z * q2.y + w4[k].w * q3.y + w1[k] * q4.y;
            const float Z = w4[k].x * q0.z + w4[k].y * q1.z + w4[k].z * q2.z + w4[k].w * q3.z + w1[k] * q4.z;
            const float W = w4[k].x * q0.w + w4[k].y * q1.w + w4[k].z * q2.w + w4[k].w * q3.w + w1[k] * q4.w;
            const float inv = __fdividef(1.0f, W);
            r[k * 3 + 0] = X * inv;
            r[k * 3 + 1] = Y * inv;
            r[k * 3 + 2] = Z * inv;
        }
        // 48B lane stride -> 8-lane STS phases cover all 32 banks: conflict-free.
        float4* ob = obuf[gg] + t * 3;
        ob[0] = make_float4(r[0], r[1], r[2], r[3]);
        ob[1] = make_float4(r[4], r[5], r[6], r[7]);
        ob[2] = make_float4(r[8], r[9], r[10], r[11]);
    }
    __syncthreads();

    // ---- TMA bulk store: two contiguous 6144B rows, async proxy ----
    if (t == 0) {
        asm volatile("fence.proxy.async.shared::cta;" ::: "memory");
        float4* gdst = out + (size_t)(b * GRID_N + g0) * ROWF4;
        const uint32_t s0 = (uint32_t)__cvta_generic_to_shared(&obuf[0][0]);
        const uint32_t s1 = (uint32_t)__cvta_generic_to_shared(&obuf[1][0]);
        asm volatile("cp.async.bulk.global.shared::cta.bulk_group [%0], [%1], %2;"
                     :: "l"(gdst), "r"(s0), "r"(ROWF4 * 16) : "memory");
        asm volatile("cp.async.bulk.global.shared::cta.bulk_group [%0], [%1], %2;"
                     :: "l"(gdst + ROWF4), "r"(s1), "r"(ROWF4 * 16) : "memory");
        asm volatile("cp.async.bulk.commit_group;" ::: "memory");
        asm volatile("cp.async.bulk.wait_group 0;" ::: "memory");
    }
}

extern "C" void kernel_launch(void* const* d_in, const int* in_sizes, int n_in,
                              void* d_out, int out_size) {
    const float4* ctrl   = (const float4*)d_in[0];
    const int*    uspan  = (const int*)d_in[1];
    const int4*   vspan4 = (const int4*)d_in[2];
    const float4* Nu     = (const float4*)d_in[3];
    const float4* Nv     = (const float4*)d_in[4];

    const int B = in_sizes[0] / (MCTRL * NCTRL * 4);  // ctrl_pts elements = B*64*64*4

    weight_kernel<<<1, 128>>>(vspan4, Nv);
    dim3 grid(GRID_N / 2, B);
    surf_eval_kernel<<<grid, 128>>>(ctrl, uspan, Nu, (float4*)d_out);
}

// round 10
// speedup vs baseline: 1.1818x; 1.1818x over previous
#include <cuda_runtime.h>
#include <cstdint>

// SurfEval: NURBS surface evaluation. B=8, M=N=64, P=Q=3, GRID=512, DIM=3.
//
// R10: dynamic-instruction reduction via packed f32x2 (FFMA2) with ZERO
// runtime duplication:
//  - weight table pairs the two h-points of each k-pair in the f32x2 lanes
//    (dup done once in weight_kernel),
//  - Su stored in smem component-split AND lane-duplicated ((x,x) u64), so
//    LDS.64 feeds fma.rn.f32x2 directly.
// One 5-tap fma2 chain = one component for TWO h-points: 40 fma2 replaces
// 160 FFMA per thread; divide epilogue vectorized too.

#define GRID_N 512
#define MCTRL 64
#define NCTRL 64
#define ROWF4 (GRID_N * 3 / 4)   // 384 float4 per (b,g) output row

typedef unsigned long long u64;

__device__ __forceinline__ u64 pack2(float lo, float hi) {
    u64 r; asm("mov.b64 %0, {%1, %2};" : "=l"(r) : "f"(lo), "f"(hi)); return r;
}
__device__ __forceinline__ void unpack2(u64 v, float& lo, float& hi) {
    asm("mov.b64 {%0, %1}, %2;" : "=f"(lo), "=f"(hi) : "l"(v));
}
__device__ __forceinline__ u64 fma2(u64 a, u64 b, u64 c) {
    u64 d; asm("fma.rn.f32x2 %0, %1, %2, %3;" : "=l"(d) : "l"(a), "l"(b), "l"(c)); return d;
}
__device__ __forceinline__ u64 mul2(u64 a, u64 b) {
    u64 d; asm("mul.rn.f32x2 %0, %1, %2;" : "=l"(d) : "l"(a), "l"(b)); return d;
}

// 5-tap chain: ((((w0*p0)+w1*p1)+w2*p2)+w3*p3)+w4*p4  (two h-points at once)
__device__ __forceinline__ u64 chain5(const u64* w, u64 p0, u64 p1, u64 p2, u64 p3, u64 p4) {
    u64 a = mul2(w[0], p0);
    a = fma2(w[1], p1, a);
    a = fma2(w[2], p2, a);
    a = fma2(w[3], p3, a);
    a = fma2(w[4], p4, a);
    return a;
}

// Precomputed Stage-B tables: k-paired, lane-duplicated 5-tap weights + window base.
__device__ u64 g_W2[2][5][128];   // (w[2kp][tap], w[2kp+1][tap]) for thread t
__device__ int g_J[128];          // j0 = vspan[4t] - 3

// ---------------- Kernel 0: weight table (1 block, 128 threads) ----------------
__global__ void weight_kernel(const int4* __restrict__ vspan4,
                              const float4* __restrict__ Nv)
{
    const int t = threadIdx.x;
    const int4 vsv = __ldg(vspan4 + t);
    g_J[t] = vsv.x - 3;
    const int vs[4] = {vsv.x, vsv.y, vsv.z, vsv.w};
    float w[4][5];
#pragma unroll
    for (int k = 0; k < 4; ++k) {
        const float4 nv = __ldg(Nv + 4 * t + k);
        const bool s = (vs[k] != vsv.x);   // span delta 0 or 1 (guaranteed)
        w[k][0] = s ? 0.0f : nv.x;
        w[k][1] = s ? nv.x : nv.y;
        w[k][2] = s ? nv.y : nv.z;
        w[k][3] = s ? nv.z : nv.w;
        w[k][4] = s ? nv.w : 0.0f;
    }
#pragma unroll
    for (int kp = 0; kp < 2; ++kp)
#pragma unroll
        for (int tap = 0; tap < 5; ++tap)
            g_W2[kp][tap][t] = pack2(w[2 * kp][tap], w[2 * kp + 1][tap]);
}

// ---------------- Kernel 1: fused surface eval (g-pair blocks) ----------------
__global__ __launch_bounds__(128, 7) void surf_eval_kernel(
    const float4* __restrict__ ctrl,   // (B, 64, 64) float4
    const int*    __restrict__ uspan,  // (512)
    const float4* __restrict__ Nu,     // (512) float4
    float4*       __restrict__ out)    // (B*512*512*3)/4 float4
{
    // component-split, lane-duplicated Su; slot 64 is the zero guard
    __shared__ u64 SuX[2][65], SuY[2][65], SuZ[2][65], SuW[2][65];

    const int g0 = blockIdx.x << 1;
    const int b  = blockIdx.y;
    const int t  = threadIdx.x;

    // ---- Prefetch Stage-B tables (coalesced; overlaps Stage-A latency) ----
    const int j0 = __ldg(g_J + t);
    u64 wA[5], wB[5];                  // k-pair (0,1) and (2,3) weights
#pragma unroll
    for (int tap = 0; tap < 5; ++tap) {
        wA[tap] = __ldg(&g_W2[0][tap][t]);
        wB[tap] = __ldg(&g_W2[1][tap][t]);
    }

    // ---- Stage A: Su[gg][n] = sum_r Nu[g0+gg,r] * ctrl[b, us-3+r, n, :] ----
    {
        const int us0 = __ldg(uspan + g0);
        const int us1 = __ldg(uspan + g0 + 1);
        const int n    = t & 63;
        const int half = t >> 6;

#define STORE_ROW(gg, nu, c0, c1, c2, c3)                                         \
        {                                                                         \
            const float ax = nu.x * c0.x + nu.y * c1.x + nu.z * c2.x + nu.w * c3.x; \
            const float ay = nu.x * c0.y + nu.y * c1.y + nu.z * c2.y + nu.w * c3.y; \
            const float az = nu.x * c0.z + nu.y * c1.z + nu.z * c2.z + nu.w * c3.z; \
            const float aw = nu.x * c0.w + nu.y * c1.w + nu.z * c2.w + nu.w * c3.w; \
            SuX[gg][n] = pack2(ax, ax);                                           \
            SuY[gg][n] = pack2(ay, ay);                                           \
            SuZ[gg][n] = pack2(az, az);                                           \
            SuW[gg][n] = pack2(aw, aw);                                           \
        }

        if (us0 == us1) {
            if (half == 0) {
                const float4 nu0 = __ldg(Nu + g0);
                const float4 nu1 = __ldg(Nu + g0 + 1);
                const float4* base = ctrl + (b * MCTRL + (us0 - 3)) * NCTRL + n;
                const float4 c0 = __ldg(base);
                const float4 c1 = __ldg(base + NCTRL);
                const float4 c2 = __ldg(base + 2 * NCTRL);
                const float4 c3 = __ldg(base + 3 * NCTRL);
                STORE_ROW(0, nu0, c0, c1, c2, c3);
                STORE_ROW(1, nu1, c0, c1, c2, c3);
            }
        } else {
            const int    us = half ? us1 : us0;
            const float4 nu = __ldg(Nu + g0 + half);
            const float4* base = ctrl + (b * MCTRL + (us - 3)) * NCTRL + n;
            const float4 c0 = __ldg(base);
            const float4 c1 = __ldg(base + NCTRL);
            const float4 c2 = __ldg(base + 2 * NCTRL);
            const float4 c3 = __ldg(base + 3 * NCTRL);
            STORE_ROW(half, nu, c0, c1, c2, c3);
        }
#undef STORE_ROW

        if (t >= 120) {   // 8 zero guards: arrays x gg
            const int idx = t - 120;
            const int gg  = idx >> 2;
            const int a   = idx & 3;
            u64* basep = (a == 0) ? SuX[gg] : (a == 1) ? SuY[gg] : (a == 2) ? SuZ[gg] : SuW[gg];
            basep[64] = 0ULL;
        }
    }
    __syncthreads();

    // ---- Stage B: 4 h points x 2 g-lines, fully packed f32x2 ----
    float4* o = out + (b * GRID_N + g0) * ROWF4 + t * 3;

#pragma unroll
    for (int gg = 0; gg < 2; ++gg) {
        // X component for both k-pairs
        u64 Xp0, Xp1, Yp0, Yp1, Zp0, Zp1, Wp0, Wp1;
        {
            const u64* s = &SuX[gg][j0];
            const u64 p0 = s[0], p1 = s[1], p2 = s[2], p3 = s[3], p4 = s[4];
            Xp0 = chain5(wA, p0, p1, p2, p3, p4);
            Xp1 = chain5(wB, p0, p1, p2, p3, p4);
        }
        {
            const u64* s = &SuY[gg][j0];
            const u64 p0 = s[0], p1 = s[1], p2 = s[2], p3 = s[3], p4 = s[4];
            Yp0 = chain5(wA, p0, p1, p2, p3, p4);
            Yp1 = chain5(wB, p0, p1, p2, p3, p4);
        }
        {
            const u64* s = &SuZ[gg][j0];
            const u64 p0 = s[0], p1 = s[1], p2 = s[2], p3 = s[3], p4 = s[4];
            Zp0 = chain5(wA, p0, p1, p2, p3, p4);
            Zp1 = chain5(wB, p0, p1, p2, p3, p4);
        }
        {
            const u64* s = &SuW[gg][j0];
            const u64 p0 = s[0], p1 = s[1], p2 = s[2], p3 = s[3], p4 = s[4];
            Wp0 = chain5(wA, p0, p1, p2, p3, p4);
            Wp1 = chain5(wB, p0, p1, p2, p3, p4);
        }

        // homogeneous divide for the 4 points
        float W0, W1, W2f, W3f;
        unpack2(Wp0, W0, W1);
        unpack2(Wp1, W2f, W3f);
        const float i0 = __fdividef(1.0f, W0);
        const float i1 = __fdividef(1.0f, W1);
        const float i2 = __fdividef(1.0f, W2f);
        const float i3 = __fdividef(1.0f, W3f);
        const u64 i01 = pack2(i0, i1);
        const u64 i23 = pack2(i2, i3);

        const u64 Xr0 = mul2(Xp0, i01), Yr0 = mul2(Yp0, i01), Zr0 = mul2(Zp0, i01);
        const u64 Xr1 = mul2(Xp1, i23), Yr1 = mul2(Yp1, i23), Zr1 = mul2(Zp1, i23);

        float x0, x1, y0, y1, z0, z1, x2, x3, y2, y3, z2, z3;
        unpack2(Xr0, x0, x1); unpack2(Yr0, y0, y1); unpack2(Zr0, z0, z1);
        unpack2(Xr1, x2, x3); unpack2(Yr1, y2, y3); unpack2(Zr1, z2, z3);

        o[0] = make_float4(x0, y0, z0, x1);
        o[1] = make_float4(y1, z1, x2, y2);
        o[2] = make_float4(z2, x3, y3, z3);
        o += ROWF4;
    }
}

extern "C" void kernel_launch(void* const* d_in, const int* in_sizes, int n_in,
                              void* d_out, int out_size) {
    const float4* ctrl   = (const float4*)d_in[0];
    const int*    uspan  = (const int*)d_in[1];
    const int4*   vspan4 = (const int4*)d_in[2];
    const float4* Nu     = (const float4*)d_in[3];
    const float4* Nv     = (const float4*)d_in[4];

    const int B = in_sizes[0] / (MCTRL * NCTRL * 4);  // ctrl_pts elements = B*64*64*4

    weight_kernel<<<1, 128>>>(vspan4, Nv);
    dim3 grid(GRID_N / 2, B);
    surf_eval_kernel<<<grid, 128>>>(ctrl, uspan, Nu, (float4*)d_out);
}

// round 11
// speedup vs baseline: 1.5918x; 1.3469x over previous
#include <cuda_runtime.h>
#include <cstdint>

// SurfEval: NURBS surface evaluation. B=8, M=N=64, P=Q=3, GRID=512, DIM=3.
//
// R11: persistent pipelined blocks + double-buffered TMA bulk stores, ONE kernel.
// Each block runs 2 g-pair tiles; tile i's 12KB output row-pair drains via
// cp.async.bulk while tile i+1 computes (no intra-loop wait with 2 buffers).
// Weights (t-only) computed once per block, shared by both tiles.

#define GRID_N 512
#define MCTRL 64
#define NCTRL 64
#define ROWF4 (GRID_N * 3 / 4)     // 384 float4 per (b,g) output row
#define TILES_PER_BLOCK 2

__global__ __launch_bounds__(128, 8) void surf_eval_kernel(
    const float4* __restrict__ ctrl,   // (B, 64, 64) float4
    const int*    __restrict__ uspan,  // (512)
    const int4*   __restrict__ vspan4, // (512) ints viewed as (128) int4
    const float4* __restrict__ Nu,     // (512) float4
    const float4* __restrict__ Nv,     // (512) float4
    float4*       __restrict__ out,    // (B*512*512*3)/4 float4
    int n_blocks)                      // gridDim.x (tiles = 2*n_blocks)
{
    __shared__ float4 Su[2][NCTRL + 1];          // [gg][n], +1 zero guard
    __shared__ float4 obuf[2][2 * ROWF4];        // [parity][row-pair], 12288B each

    const int t = threadIdx.x;

    // ---- per-block (tile-invariant) Stage-B setup: weights + window base ----
    const int4 vsv = __ldg(vspan4 + t);
    const int  j0  = vsv.x - 3;
    float w[4][5];
    {
        const int h0 = t << 2;
        const int vd[4] = {0, vsv.y - vsv.x, vsv.z - vsv.x, vsv.w - vsv.x};
#pragma unroll
        for (int k = 0; k < 4; ++k) {
            const float4 nv = __ldg(Nv + h0 + k);
            const bool s = (vd[k] != 0);           // span delta 0 or 1
            w[k][0] = s ? 0.0f : nv.x;
            w[k][1] = s ? nv.x : nv.y;
            w[k][2] = s ? nv.y : nv.z;
            w[k][3] = s ? nv.z : nv.w;
            w[k][4] = s ? nv.w : 0.0f;
        }
    }

#pragma unroll
    for (int it = 0; it < TILES_PER_BLOCK; ++it) {
        const int tile = blockIdx.x + it * n_blocks;   // 0 .. 2*n_blocks-1
        const int g0   = (tile & 255) << 1;            // g-pair base
        const int b    = tile >> 8;                    // batch

        // ---- Stage A: Su[gg][n] = sum_r Nu[g0+gg,r] * ctrl[b, us-3+r, n, :] ----
        {
            const int us0 = __ldg(uspan + g0);
            const int us1 = __ldg(uspan + g0 + 1);
            const int n    = t & 63;
            const int half = t >> 6;

            if (us0 == us1) {
                if (half == 0) {
                    const float4 nu0 = __ldg(Nu + g0);
                    const float4 nu1 = __ldg(Nu + g0 + 1);
                    const float4* base = ctrl + (b * MCTRL + (us0 - 3)) * NCTRL + n;
                    const float4 c0 = __ldg(base);
                    const float4 c1 = __ldg(base + NCTRL);
                    const float4 c2 = __ldg(base + 2 * NCTRL);
                    const float4 c3 = __ldg(base + 3 * NCTRL);
                    float4 a;
                    a.x = nu0.x * c0.x + nu0.y * c1.x + nu0.z * c2.x + nu0.w * c3.x;
                    a.y = nu0.x * c0.y + nu0.y * c1.y + nu0.z * c2.y + nu0.w * c3.y;
                    a.z = nu0.x * c0.z + nu0.y * c1.z + nu0.z * c2.z + nu0.w * c3.z;
                    a.w = nu0.x * c0.w + nu0.y * c1.w + nu0.z * c2.w + nu0.w * c3.w;
                    Su[0][n] = a;
                    a.x = nu1.x * c0.x + nu1.y * c1.x + nu1.z * c2.x + nu1.w * c3.x;
                    a.y = nu1.x * c0.y + nu1.y * c1.y + nu1.z * c2.y + nu1.w * c3.y;
                    a.z = nu1.x * c0.z + nu1.y * c1.z + nu1.z * c2.z + nu1.w * c3.z;
                    a.w = nu1.x * c0.w + nu1.y * c1.w + nu1.z * c2.w + nu1.w * c3.w;
                    Su[1][n] = a;
                }
            } else {
                const int    us = half ? us1 : us0;
                const float4 nu = __ldg(Nu + g0 + half);
                const float4* base = ctrl + (b * MCTRL + (us - 3)) * NCTRL + n;
                const float4 c0 = __ldg(base);
                const float4 c1 = __ldg(base + NCTRL);
                const float4 c2 = __ldg(base + 2 * NCTRL);
                const float4 c3 = __ldg(base + 3 * NCTRL);
                float4 a;
                a.x = nu.x * c0.x + nu.y * c1.x + nu.z * c2.x + nu.w * c3.x;
                a.y = nu.x * c0.y + nu.y * c1.y + nu.z * c2.y + nu.w * c3.y;
                a.z = nu.x * c0.z + nu.y * c1.z + nu.z * c2.z + nu.w * c3.z;
                a.w = nu.x * c0.w + nu.y * c1.w + nu.z * c2.w + nu.w * c3.w;
                Su[half][n] = a;
            }
            if (t == 124) Su[0][NCTRL] = make_float4(0.f, 0.f, 0.f, 0.f);
            if (t == 125) Su[1][NCTRL] = make_float4(0.f, 0.f, 0.f, 0.f);
        }
        __syncthreads();

        // ---- Stage B -> staging buffer (parity it&1) ----
        float4* ob = obuf[it & 1] + t * 3;
#pragma unroll
        for (int gg = 0; gg < 2; ++gg) {
            const float4* SuG = Su[gg];
            const float4 q0 = SuG[j0];
            const float4 q1 = SuG[j0 + 1];
            const float4 q2 = SuG[j0 + 2];
            const float4 q3 = SuG[j0 + 3];
            const float4 q4 = SuG[j0 + 4];

            float r[12];
#pragma unroll
            for (int k = 0; k < 4; ++k) {
                const float X = w[k][0] * q0.x + w[k][1] * q1.x + w[k][2] * q2.x + w[k][3] * q3.x + w[k][4] * q4.x;
                const float Y = w[k][0] * q0.y + w[k][1] * q1.y + w[k][2] * q2.y + w[k][3] * q3.y + w[k][4] * q4.y;
                const float Z = w[k][0] * q0.z + w[k][1] * q1.z + w[k][2] * q2.z + w[k][3] * q3.z + w[k][4] * q4.z;
                const float W = w[k][0] * q0.w + w[k][1] * q1.w + w[k][2] * q2.w + w[k][3] * q3.w + w[k][4] * q4.w;
                const float inv = __fdividef(1.0f, W);
                r[k * 3 + 0] = X * inv;
                r[k * 3 + 1] = Y * inv;
                r[k * 3 + 2] = Z * inv;
            }
            ob[0] = make_float4(r[0], r[1], r[2], r[3]);
            ob[1] = make_float4(r[4], r[5], r[6], r[7]);
            ob[2] = make_float4(r[8], r[9], r[10], r[11]);
            ob += ROWF4;
        }
        __syncthreads();   // obuf complete; also protects Su for next tile's Stage A

        // ---- one 12288B bulk store for the contiguous row pair (async drain) ----
        if (t == 0) {
            asm volatile("fence.proxy.async.shared::cta;" ::: "memory");
            float4* gdst = out + (size_t)(b * GRID_N + g0) * ROWF4;
            const uint32_t s = (uint32_t)__cvta_generic_to_shared(&obuf[it & 1][0]);
            asm volatile("cp.async.bulk.global.shared::cta.bulk_group [%0], [%1], %2;"
                         :: "l"(gdst), "r"(s), "r"(2 * ROWF4 * 16) : "memory");
            asm volatile("cp.async.bulk.commit_group;" ::: "memory");
        }
    }

    // drain outstanding stores before the CTA (and its smem) retires
    if (t == 0) {
        asm volatile("cp.async.bulk.wait_group 0;" ::: "memory");
    }
}

extern "C" void kernel_launch(void* const* d_in, const int* in_sizes, int n_in,
                              void* d_out, int out_size) {
    const float4* ctrl   = (const float4*)d_in[0];
    const int*    uspan  = (const int*)d_in[1];
    const int4*   vspan4 = (const int4*)d_in[2];
    const float4* Nu     = (const float4*)d_in[3];
    const float4* Nv     = (const float4*)d_in[4];

    const int B = in_sizes[0] / (MCTRL * NCTRL * 4);  // ctrl_pts elements = B*64*64*4
    const int tiles = B * (GRID_N / 2);               // 2048 for B=8
    const int n_blocks = tiles / TILES_PER_BLOCK;     // 1024

    surf_eval_kernel<<<n_blocks, 128>>>(ctrl, uspan, vspan4, Nu, Nv,
                                        (float4*)d_out, n_blocks);
}

// round 12
// speedup vs baseline: 1.6299x; 1.0239x over previous
#include <cuda_runtime.h>
#include <cstdint>

// SurfEval: NURBS surface evaluation. B=8, M=N=64, P=Q=3, GRID=512, DIM=3.
//
// R12 = R11 (persistent 2-tile blocks + double-buffered cp.async.bulk output
// stores) + cp.async (LDGSTS) PREFETCH of the next tile's 5-row ctrl window
// into smem, issued after the current tile's Stage A consumes the buffer.
// Stage A becomes pure LDS with its gmem latency hidden behind Stage B + TMA.

#define GRID_N 512
#define MCTRL 64
#define NCTRL 64
#define ROWF4 (GRID_N * 3 / 4)     // 384 float4 per (b,g) output row
#define TILES_PER_BLOCK 2
#define CWIN (5 * 64)              // 5 ctrl rows x 64 float4 = 5KB window

__device__ __forceinline__ void prefetch_ctrl(const float4* __restrict__ ctrl,
                                              const int* __restrict__ uspan,
                                              int tile, float4* cbuf, int t)
{
    const int g0  = (tile & 255) << 1;
    const int b   = tile >> 8;
    const int us0 = __ldg(uspan + g0);
    const int base = b * MCTRL * NCTRL;
#pragma unroll
    for (int i = t; i < CWIN; i += 128) {
        const int row = i >> 6;
        const int col = i & 63;
        int gr = us0 - 3 + row;            // us0 >= 3 always
        if (gr > 63) gr = 63;              // row 4 may overflow when us0 == 63
        const float4* src = ctrl + base + gr * NCTRL + col;
        const uint32_t dst = (uint32_t)__cvta_generic_to_shared(cbuf + i);
        asm volatile("cp.async.cg.shared.global [%0], [%1], 16;"
                     :: "r"(dst), "l"(src) : "memory");
    }
    asm volatile("cp.async.commit_group;" ::: "memory");
}

__global__ __launch_bounds__(128, 7) void surf_eval_kernel(
    const float4* __restrict__ ctrl,   // (B, 64, 64) float4
    const int*    __restrict__ uspan,  // (512)
    const int4*   __restrict__ vspan4, // (512) ints viewed as (128) int4
    const float4* __restrict__ Nu,     // (512) float4
    const float4* __restrict__ Nv,     // (512) float4
    float4*       __restrict__ out,    // (B*512*512*3)/4 float4
    int n_blocks)                      // gridDim.x (tiles = 2*n_blocks)
{
    __shared__ float4 Su[2][NCTRL + 1];      // [gg][n], +1 zero guard
    __shared__ float4 obuf[2][2 * ROWF4];    // [parity][row-pair], 12288B each
    __shared__ float4 cbuf[CWIN];            // prefetched 5-row ctrl window

    const int t = threadIdx.x;

    // ---- prologue: prefetch tile 0's ctrl window ----
    prefetch_ctrl(ctrl, uspan, blockIdx.x, cbuf, t);

    // ---- per-block (tile-invariant) Stage-B setup: weights + window base ----
    const int4 vsv = __ldg(vspan4 + t);
    const int  j0  = vsv.x - 3;
    float w[4][5];
    {
        const int h0 = t << 2;
        const int vd[4] = {0, vsv.y - vsv.x, vsv.z - vsv.x, vsv.w - vsv.x};
#pragma unroll
        for (int k = 0; k < 4; ++k) {
            const float4 nv = __ldg(Nv + h0 + k);
            const bool s = (vd[k] != 0);           // span delta 0 or 1
            w[k][0] = s ? 0.0f : nv.x;
            w[k][1] = s ? nv.x : nv.y;
            w[k][2] = s ? nv.y : nv.z;
            w[k][3] = s ? nv.z : nv.w;
            w[k][4] = s ? nv.w : 0.0f;
        }
    }

#pragma unroll
    for (int it = 0; it < TILES_PER_BLOCK; ++it) {
        const int tile = blockIdx.x + it * n_blocks;   // 0 .. 2*n_blocks-1
        const int g0   = (tile & 255) << 1;            // g-pair base
        const int b    = tile >> 8;                    // batch

        const int us0 = __ldg(uspan + g0);
        const int us1 = __ldg(uspan + g0 + 1);

        // ---- wait for this tile's ctrl window ----
        asm volatile("cp.async.wait_group 0;" ::: "memory");
        __syncthreads();

        // ---- Stage A (pure LDS): Su[gg][n] from cbuf rows ----
        {
            const int n    = t & 63;
            const int half = t >> 6;

            if (us0 == us1) {
                if (half == 0) {
                    const float4 nu0 = __ldg(Nu + g0);
                    const float4 nu1 = __ldg(Nu + g0 + 1);
                    const float4 c0 = cbuf[n];
                    const float4 c1 = cbuf[64 + n];
                    const float4 c2 = cbuf[128 + n];
                    const float4 c3 = cbuf[192 + n];
                    float4 a;
                    a.x = nu0.x * c0.x + nu0.y * c1.x + nu0.z * c2.x + nu0.w * c3.x;
                    a.y = nu0.x * c0.y + nu0.y * c1.y + nu0.z * c2.y + nu0.w * c3.y;
                    a.z = nu0.x * c0.z + nu0.y * c1.z + nu0.z * c2.z + nu0.w * c3.z;
                    a.w = nu0.x * c0.w + nu0.y * c1.w + nu0.z * c2.w + nu0.w * c3.w;
                    Su[0][n] = a;
                    a.x = nu1.x * c0.x + nu1.y * c1.x + nu1.z * c2.x + nu1.w * c3.x;
                    a.y = nu1.x * c0.y + nu1.y * c1.y + nu1.z * c2.y + nu1.w * c3.y;
                    a.z = nu1.x * c0.z + nu1.y * c1.z + nu1.z * c2.z + nu1.w * c3.z;
                    a.w = nu1.x * c0.w + nu1.y * c1.w + nu1.z * c2.w + nu1.w * c3.w;
                    Su[1][n] = a;
                }
            } else {
                // us1 = us0 + 1: half 0 reads rows 0..3, half 1 reads rows 1..4
                const float4 nu = __ldg(Nu + g0 + half);
                const int roff = half * 64;
                const float4 c0 = cbuf[roff + n];
                const float4 c1 = cbuf[roff + 64 + n];
                const float4 c2 = cbuf[roff + 128 + n];
                const float4 c3 = cbuf[roff + 192 + n];
                float4 a;
                a.x = nu.x * c0.x + nu.y * c1.x + nu.z * c2.x + nu.w * c3.x;
                a.y = nu.x * c0.y + nu.y * c1.y + nu.z * c2.y + nu.w * c3.y;
                a.z = nu.x * c0.z + nu.y * c1.z + nu.z * c2.z + nu.w * c3.z;
                a.w = nu.x * c0.w + nu.y * c1.w + nu.z * c2.w + nu.w * c3.w;
                Su[half][n] = a;
            }
            if (t == 124) Su[0][NCTRL] = make_float4(0.f, 0.f, 0.f, 0.f);
            if (t == 125) Su[1][NCTRL] = make_float4(0.f, 0.f, 0.f, 0.f);
        }
        __syncthreads();   // Su ready; cbuf fully consumed

        // ---- prefetch NEXT tile's ctrl window (drains behind Stage B + store) ----
        if (it + 1 < TILES_PER_BLOCK)
            prefetch_ctrl(ctrl, uspan, blockIdx.x + (it + 1) * n_blocks, cbuf, t);

        // ---- Stage B -> staging buffer (parity it&1) ----
        float4* ob = obuf[it & 1] + t * 3;
#pragma unroll
        for (int gg = 0; gg < 2; ++gg) {
            const float4* SuG = Su[gg];
            const float4 q0 = SuG[j0];
            const float4 q1 = SuG[j0 + 1];
            const float4 q2 = SuG[j0 + 2];
            const float4 q3 = SuG[j0 + 3];
            const float4 q4 = SuG[j0 + 4];

            float r[12];
#pragma unroll
            for (int k = 0; k < 4; ++k) {
                const float X = w[k][0] * q0.x + w[k][1] * q1.x + w[k][2] * q2.x + w[k][3] * q3.x + w[k][4] * q4.x;
                const float Y = w[k][0] * q0.y + w[k][1] * q1.y + w[k][2] * q2.y + w[k][3] * q3.y + w[k][4] * q4.y;
                const float Z = w[k][0] * q0.z + w[k][1] * q1.z + w[k][2] * q2.z + w[k][3] * q3.z + w[k][4] * q4.z;
                const float W = w[k][0] * q0.w + w[k][1] * q1.w + w[k][2] * q2.w + w[k][3] * q3.w + w[k][4] * q4.w;
                const float inv = __fdividef(1.0f, W);
                r[k * 3 + 0] = X * inv;
                r[k * 3 + 1] = Y * inv;
                r[k * 3 + 2] = Z * inv;
            }
            ob[0] = make_float4(r[0], r[1], r[2], r[3]);
            ob[1] = make_float4(r[4], r[5], r[6], r[7]);
            ob[2] = make_float4(r[8], r[9], r[10], r[11]);
            ob += ROWF4;
        }
        __syncthreads();   // obuf complete; Su free for next tile

        // ---- one 12288B bulk store for the contiguous row pair (async drain) ----
        if (t == 0) {
            asm volatile("fence.proxy.async.shared::cta;" ::: "memory");
            float4* gdst = out + (size_t)(b * GRID_N + g0) * ROWF4;
            const uint32_t s = (uint32_t)__cvta_generic_to_shared(&obuf[it & 1][0]);
            asm volatile("cp.async.bulk.global.shared::cta.bulk_group [%0], [%1], %2;"
                         :: "l"(gdst), "r"(s), "r"(2 * ROWF4 * 16) : "memory");
            asm volatile("cp.async.bulk.commit_group;" ::: "memory");
        }
    }

    // drain outstanding bulk stores before the CTA (and its smem) retires
    if (t == 0) {
        asm volatile("cp.async.bulk.wait_group 0;" ::: "memory");
    }
}

extern "C" void kernel_launch(void* const* d_in, const int* in_sizes, int n_in,
                              void* d_out, int out_size) {
    const float4* ctrl   = (const float4*)d_in[0];
    const int*    uspan  = (const int*)d_in[1];
    const int4*   vspan4 = (const int4*)d_in[2];
    const float4* Nu     = (const float4*)d_in[3];
    const float4* Nv     = (const float4*)d_in[4];

    const int B = in_sizes[0] / (MCTRL * NCTRL * 4);  // ctrl_pts elements = B*64*64*4
    const int tiles = B * (GRID_N / 2);               // 2048 for B=8
    const int n_blocks = tiles / TILES_PER_BLOCK;     // 1024

    surf_eval_kernel<<<n_blocks, 128>>>(ctrl, uspan, vspan4, Nu, Nv,
                                        (float4*)d_out, n_blocks);
}